// round 6
// baseline (speedup 1.0000x reference)
#include <cuda_runtime.h>

#define NUM_NODES 100000
#define NUM_EDGES 6400000
#define NUM_STEPS 10

#define SRC_TILE 25000             // src nodes per tile (100KB cur window, L1-resident)
#define NTILES 4                   // NUM_NODES / SRC_TILE
#define CTAS_PER_TILE 148
#define STEP_TPB 512

#define NBINS (NTILES * NUM_NODES) // 400,000 bins: key = src_tile*N + dst
#define SCAN_BLK 1024
#define NSB ((NBINS + SCAN_BLK - 1) / SCAN_BLK)   // 391

// Scratch (allocation-free rule: __device__ globals)
__device__ int2  g_edges[NUM_EDGES];      // {bin, packed src_local<<17 | dst}
__device__ uint2 g_sp2[NUM_EDGES];        // {packed, prob-bits}, sorted by bin
__device__ int   g_bins[NBINS];
__device__ int   g_binptr[NBINS + 1];
__device__ int   g_cursor[NBINS];
__device__ int   g_blocksum[NSB];
__device__ float g_curA[NUM_NODES];
__device__ float g_curB[NUM_NODES];
__device__ float g_surv[NUM_NODES];
__device__ float g_acc[NUM_NODES];
__device__ int   g_is64;

// ---------------------------------------------------------------------------
// Detect edge_index element width (int64 vs int32): int64 values < 1e5 have
// every odd 32-bit word == 0.
// ---------------------------------------------------------------------------
__global__ void detect_kernel(const int* __restrict__ w) {
    __shared__ int nz;
    if (threadIdx.x == 0) nz = 0;
    __syncthreads();
    for (int i = threadIdx.x; i < 4096; i += blockDim.x)
        if (w[2 * i + 1] != 0) nz = 1;
    __syncthreads();
    if (threadIdx.x == 0) g_is64 = nz ? 0 : 1;
}

__global__ void zero_bins_kernel() {
    int i = blockIdx.x * blockDim.x + threadIdx.x;
    if (i < NBINS) g_bins[i] = 0;
}

// ---------------------------------------------------------------------------
// Convert edges -> {bin, packed} AND histogram bins.
// bin = src_tile * NUM_NODES + dst   (primary: src tile, secondary: dst)
// packed = src_local << 17 | dst     (src_local < 32768, dst < 131072)
// ---------------------------------------------------------------------------
__global__ void convert_hist_kernel(const void* __restrict__ eidx) {
    int i = blockIdx.x * blockDim.x + threadIdx.x;
    if (i >= NUM_EDGES) return;
    int s, d;
    if (g_is64) {
        const long long* e = (const long long*)eidx;
        s = (int)e[i];
        d = (int)e[NUM_EDGES + i];
    } else {
        const int* e = (const int*)eidx;
        s = e[i];
        d = e[NUM_EDGES + i];
    }
    s = min(max(s, 0), NUM_NODES - 1);
    d = min(max(d, 0), NUM_NODES - 1);
    int tile = s / SRC_TILE;
    int sl   = s - tile * SRC_TILE;
    int bin  = tile * NUM_NODES + d;
    g_edges[i] = make_int2(bin, (sl << 17) | d);
    atomicAdd(&g_bins[bin], 1);
}

// ---------------------------------------------------------------------------
// 3-phase exclusive scan of g_bins -> g_binptr (+ cursor copy)
// ---------------------------------------------------------------------------
__global__ void scan1_kernel() {
    __shared__ int s[SCAN_BLK];
    int tid = threadIdx.x;
    int i = blockIdx.x * SCAN_BLK + tid;
    int v = (i < NBINS) ? g_bins[i] : 0;
    s[tid] = v;
    __syncthreads();
    #pragma unroll
    for (int off = 1; off < SCAN_BLK; off <<= 1) {
        int t = (tid >= off) ? s[tid - off] : 0;
        __syncthreads();
        s[tid] += t;
        __syncthreads();
    }
    if (i < NBINS) g_binptr[i] = s[tid] - v;   // exclusive, sans block offset
    if (tid == SCAN_BLK - 1) g_blocksum[blockIdx.x] = s[tid];
}

__global__ void scan2_kernel() {
    __shared__ int s[SCAN_BLK];
    int tid = threadIdx.x;
    int v = (tid < NSB) ? g_blocksum[tid] : 0;
    s[tid] = v;
    __syncthreads();
    #pragma unroll
    for (int off = 1; off < SCAN_BLK; off <<= 1) {
        int t = (tid >= off) ? s[tid - off] : 0;
        __syncthreads();
        s[tid] += t;
        __syncthreads();
    }
    if (tid < NSB) g_blocksum[tid] = s[tid] - v;  // exclusive block offsets
    if (tid == 0) g_binptr[NBINS] = NUM_EDGES;
}

__global__ void scan3_kernel() {
    int i = blockIdx.x * blockDim.x + threadIdx.x;
    if (i >= NBINS) return;
    int r = g_binptr[i] + g_blocksum[i / SCAN_BLK];
    g_binptr[i] = r;
    g_cursor[i] = r;
}

// ---------------------------------------------------------------------------
// Scatter into (src_tile, dst)-sorted order.
// ---------------------------------------------------------------------------
__global__ void scatter_kernel(const float* __restrict__ probs) {
    int i = blockIdx.x * blockDim.x + threadIdx.x;
    if (i >= NUM_EDGES) return;
    int2 e = g_edges[i];
    float p = probs[i];
    int pos = atomicAdd(&g_cursor[e.x], 1);
    g_sp2[pos] = make_uint2((unsigned)e.y, (unsigned)__float_as_int(p));
}

__global__ void init_nodes_kernel(const float* __restrict__ x) {
    int n = blockIdx.x * blockDim.x + threadIdx.x;
    if (n >= NUM_NODES) return;
    float xv = x[n];
    g_curA[n] = xv;
    g_surv[n] = 1.0f - xv;
    g_acc[n]  = 0.0f;
}

// ---------------------------------------------------------------------------
// Per-step edge pass:
//  - CTA works a contiguous slice of one src tile's edges (gather L1-resident)
//  - dst runs are contiguous -> warp-segmented shuffle reduction, head lanes
//    issue one global atomicAdd per run (~600K atomics/step vs 6.4M)
// ---------------------------------------------------------------------------
__global__ void __launch_bounds__(STEP_TPB)
spmv_kernel(int step) {
    int tile = blockIdx.x / CTAS_PER_TILE;
    int sub  = blockIdx.x % CTAS_PER_TILE;

    const float* cur  = (step & 1) ? g_curB : g_curA;
    const float* curt = cur + tile * SRC_TILE;

    int start = g_binptr[tile * NUM_NODES];
    int end   = g_binptr[(tile + 1) * NUM_NODES];
    int n = end - start;
    int per = (n + CTAS_PER_TILE - 1) / CTAS_PER_TILE;
    int a = start + sub * per;
    int b = min(a + per, end);

    int wid  = threadIdx.x >> 5;
    int lane = threadIdx.x & 31;
    const int NW = STEP_TPB / 32;

    for (int j0 = a + wid * 32; j0 < b; j0 += NW * 32) {
        int j = j0 + lane;
        bool valid = j < b;
        uint2 e = valid ? g_sp2[j] : make_uint2(0u, 0u);
        int dst = valid ? (int)(e.x & 0x1FFFFu) : -1;
        float v = valid ? __ldg(&curt[e.x >> 17]) * __int_as_float((int)e.y)
                        : 0.0f;

        // segmented reduce over contiguous equal-dst runs
        #pragma unroll
        for (int o = 1; o < 32; o <<= 1) {
            float vo = __shfl_down_sync(0xffffffffu, v, o);
            int   dd = __shfl_down_sync(0xffffffffu, dst, o);
            if (lane + o < 32 && dd == dst) v += vo;
        }
        int dp = __shfl_up_sync(0xffffffffu, dst, 1);
        bool head = (lane == 0) || (dp != dst);
        if (valid && head) atomicAdd(&g_acc[dst], v);
    }
}

// ---------------------------------------------------------------------------
// Per-step node pass: cur' = scale*acc + bias; surv *= (1-cur'); acc = 0.
// Buffer parity resolved in device code (host &symbol is invalid).
// ---------------------------------------------------------------------------
__global__ void node_kernel(const float* __restrict__ td,
                            const float* __restrict__ ew,
                            const float* __restrict__ nb,
                            int step, int is_last,
                            float* __restrict__ out) {
    int n = blockIdx.x * blockDim.x + threadIdx.x;
    if (n >= NUM_NODES) return;

    float* curn = (step & 1) ? g_curA : g_curB;

    float tdv = td[step];
    float scale = ew[step] * expf(-(tdv * tdv));
    float c = scale * g_acc[n] + nb[0];
    g_acc[n] = 0.0f;
    curn[n] = c;
    float sv = g_surv[n] * (1.0f - c);
    g_surv[n] = sv;
    if (is_last) {
        float fi = 1.0f - sv;
        out[n] = fminf(fmaxf(fi, 0.0f), 1.0f);
    }
}

// ---------------------------------------------------------------------------
// Launch
// ---------------------------------------------------------------------------
extern "C" void kernel_launch(void* const* d_in, const int* in_sizes, int n_in,
                              void* d_out, int out_size) {
    const float* x     = (const float*)d_in[0];
    const void*  eidx  = d_in[1];
    const float* probs = (const float*)d_in[2];
    const float* td    = (const float*)d_in[3];
    const float* nb    = (const float*)d_in[4];
    const float* ew    = (const float*)d_in[5];
    float*       out   = (float*)d_out;

    const int TB = 256;
    int eblocks = (NUM_EDGES + TB - 1) / TB;
    int nblocks = (NUM_NODES + TB - 1) / TB;
    int bblocks = (NBINS + TB - 1) / TB;

    detect_kernel<<<1, 256>>>((const int*)eidx);
    zero_bins_kernel<<<bblocks, TB>>>();
    convert_hist_kernel<<<eblocks, TB>>>(eidx);
    scan1_kernel<<<NSB, SCAN_BLK>>>();
    scan2_kernel<<<1, SCAN_BLK>>>();
    scan3_kernel<<<bblocks, TB>>>();
    scatter_kernel<<<eblocks, TB>>>(probs);
    init_nodes_kernel<<<nblocks, TB>>>(x);

    for (int step = 0; step < NUM_STEPS; step++) {
        spmv_kernel<<<NTILES * CTAS_PER_TILE, STEP_TPB>>>(step);
        node_kernel<<<nblocks, TB>>>(td, ew, nb, step,
                                     (step == NUM_STEPS - 1) ? 1 : 0, out);
    }
}